// round 8
// baseline (speedup 1.0000x reference)
#include <cuda_runtime.h>

typedef unsigned long long u64;

#define NWIRES  12
#define DIM     4096
#define NLAYERS 4
#define NT      256

// dynamic smem layout (bytes):
//  st  : ulonglong2[4096]  = 65536   (re-pack, im-pack per amplitude, 2 batch elems)
//  Ugp : u64[48*8]         = 3072    (packed gate constants: gx gy gz gw gyn gzn gwn pad)
//  Ugs : float4[96]        = 1536    (scalar gate staging)
//  red : float[128]        = 512
#define OFF_UGP 65536
#define OFF_UGS (65536 + 3072)
#define OFF_RED (65536 + 3072 + 1536)
#define SMEM_TOTAL (65536 + 3072 + 1536 + 512)

// ---- packed f32x2 helpers ----
__device__ __forceinline__ u64 pk2(float lo, float hi) {
    u64 r; asm("mov.b64 %0, {%1,%2};" : "=l"(r) : "f"(lo), "f"(hi)); return r;
}
__device__ __forceinline__ void up2(u64 v, float& lo, float& hi) {
    asm("mov.b64 {%0,%1}, %2;" : "=f"(lo), "=f"(hi) : "l"(v));
}
__device__ __forceinline__ u64 ffma2(u64 a, u64 b, u64 c) {
    u64 d; asm("fma.rn.f32x2 %0, %1, %2, %3;" : "=l"(d) : "l"(a), "l"(b), "l"(c)); return d;
}
__device__ __forceinline__ u64 fmul2(u64 a, u64 b) {
    u64 d; asm("mul.rn.f32x2 %0, %1, %2;" : "=l"(d) : "l"(a), "l"(b)); return d;
}

__device__ __forceinline__ float2 cmul(float2 a, float2 b) {
    return make_float2(fmaf(a.x, b.x, -(a.y * b.y)),
                       fmaf(a.x, b.y,   a.y * b.x));
}
__device__ __forceinline__ float2 cfma(float2 a, float2 b, float2 c) {
    c.x = fmaf(a.x, b.x, fmaf(-a.y, b.y, c.x));
    c.y = fmaf(a.x, b.y, fmaf( a.y, b.x, c.y));
    return c;
}

// bank-conflict-avoiding swizzle: XOR low 4 bits with bits 4-7
__device__ __forceinline__ int saddr(int j) { return j ^ ((j >> 4) & 15); }

// h = g^{-1} (prefix-XOR) of the CNOT-chain permutation, then swizzle
__device__ __forceinline__ int haddr(int j) {
    j ^= j >> 1; j ^= j >> 2; j ^= j >> 4; j ^= j >> 8;
    return saddr(j);
}

// logical index owned by thread t, local slot v, for round R
template <int R>
__device__ __forceinline__ int jidx(int t, int v) {
    if (R == 0) return (t << 4) | v;
    if (R == 1) return ((t & 0xF0) << 4) | (v << 4) | (t & 15);
    return (v << 8) | t;
}

// SU(2) butterfly over 2 batch elements, staged by shared multiplicand.
//   r0' =  gx a - gy b + gz c - gw d
//   i0' =  gy a + gx b + gw c + gz d
//   r1' = -gz a - gw b + gx c + gy d
//   i1' =  gw a - gz b - gy c + gx d
#define BFLY(i0, i1)                                                      \
    {                                                                     \
        const u64 a = re[i0], b = im[i0], c = re[i1], d = im[i1];         \
        u64 n0 = fmul2(gx, a);                                            \
        u64 n1 = fmul2(gy, a);                                            \
        u64 n2 = fmul2(gzn, a);                                           \
        u64 n3 = fmul2(gw, a);                                            \
        n0 = ffma2(gyn, b, n0);                                           \
        n1 = ffma2(gx, b, n1);                                            \
        n2 = ffma2(gwn, b, n2);                                           \
        n3 = ffma2(gzn, b, n3);                                           \
        n0 = ffma2(gz, c, n0);                                            \
        n1 = ffma2(gw, c, n1);                                            \
        n2 = ffma2(gx, c, n2);                                            \
        n3 = ffma2(gyn, c, n3);                                           \
        n0 = ffma2(gwn, d, n0);                                           \
        n1 = ffma2(gz, d, n1);                                            \
        n2 = ffma2(gy, d, n2);                                            \
        n3 = ffma2(gx, d, n3);                                            \
        re[i0] = n0; im[i0] = n1; re[i1] = n2; im[i1] = n3;               \
    }

// gather 16 packed amps; apply this round's 4 gates in registers
template <int R>
__device__ __forceinline__ void gather_apply(const ulonglong2* __restrict__ st,
                                             const u64* __restrict__ Ugp,
                                             int L, int t, u64* re, u64* im) {
    #pragma unroll
    for (int v = 0; v < 16; ++v) {
        const ulonglong2 a = st[saddr(jidx<R>(t, v))];
        re[v] = a.x; im[v] = a.y;
    }
    #pragma unroll
    for (int lb = 0; lb < 4; ++lb) {
        const int wi = 11 - (4 * R + lb);
        const u64* g = Ugp + (L * NWIRES + wi) * 8;
        const u64 gx = g[0], gy = g[1], gz = g[2], gw = g[3];
        const u64 gyn = g[4], gzn = g[5], gwn = g[6];
        const int str = 1 << lb;
        #pragma unroll
        for (int p = 0; p < 8; ++p) {
            const int i0 = ((p & ~(str - 1)) << 1) | (p & (str - 1));
            const int i1 = i0 | str;
            BFLY(i0, i1);
        }
    }
}

__global__ __launch_bounds__(NT, 2)
void qnn_kernel(const float* __restrict__ x, const float* __restrict__ w,
                float* __restrict__ out)
{
    extern __shared__ char smem[];
    ulonglong2* st  = (ulonglong2*)smem;
    u64*        Ugp = (u64*)(smem + OFF_UGP);
    float4*     Ugs = (float4*)(smem + OFF_UGS);
    float*      red = (float*)(smem + OFF_RED);

    const int b0 = blockIdx.x * 2;
    const int t  = threadIdx.x;

    // ---- build fused SU(2) gates U = RZ RY RX @ Enc for both elements ----
    if (t < 2 * NLAYERS * NWIRES) {
        const int e = t / 48, idx = t % 48;
        const int l = idx / NWIRES, wi = idx % NWIRES;
        const float* wp = w + (l * NWIRES + wi) * 3;
        float sa, ca, sb, cb, sg, cg;
        sincosf(0.5f * wp[0], &sa, &ca);
        sincosf(0.5f * wp[1], &sb, &cb);
        sincosf(0.5f * wp[2], &sg, &cg);
        float2 m00 = make_float2( cb * ca,  sb * sa);
        float2 m01 = make_float2(-sb * ca, -cb * sa);
        const float2 e0 = make_float2(cg, -sg);
        m00 = cmul(e0, m00); m01 = cmul(e0, m01);
        const float th = x[(b0 + e) * 2 + (wi & 1)];
        float se, ce;
        sincosf(0.5f * th, &se, &ce);
        float2 E00, E01, E10, E11;
        if (wi & 1) { // RY
            E00 = make_float2(ce, 0.f);  E01 = make_float2(-se, 0.f);
            E10 = make_float2(se, 0.f);  E11 = make_float2(ce, 0.f);
        } else {      // RX
            E00 = make_float2(ce, 0.f);  E01 = make_float2(0.f, -se);
            E10 = make_float2(0.f, -se); E11 = make_float2(ce, 0.f);
        }
        const float2 u00 = cfma(m01, E10, cmul(m00, E00));
        const float2 u01 = cfma(m01, E11, cmul(m00, E01));
        Ugs[e * 48 + idx] = make_float4(u00.x, u00.y, u01.x, u01.y);
    }
    __syncthreads();

    // ---- pack gate constants across the two elements (48 threads) ----
    if (t < NLAYERS * NWIRES) {
        const float4 A = Ugs[t], B = Ugs[48 + t];
        u64* g = Ugp + t * 8;
        g[0] = pk2( A.x,  B.x);   // gx
        g[1] = pk2( A.y,  B.y);   // gy
        g[2] = pk2( A.z,  B.z);   // gz
        g[3] = pk2( A.w,  B.w);   // gw
        g[4] = pk2(-A.y, -B.y);   // gyn
        g[5] = pk2(-A.z, -B.z);   // gzn
        g[6] = pk2(-A.w, -B.w);   // gwn
        g[7] = 0;
    }
    __syncthreads();

    // ---- layer 0 on |0..0>: product state, stored through CNOT map h ----
    {
        u64 pre = pk2(1.f, 1.f), pim = pk2(0.f, 0.f);
        #pragma unroll
        for (int bit = 0; bit < 8; ++bit) {
            const int row = (t >> bit) & 1;
            const u64* g = Ugp + (11 - bit) * 8;
            // column 0: row0 -> (gx, gy), -ci = gyn ; row1 -> (-gz, gw), -ci = gwn
            const u64 cr  = g[row ? 5 : 0];
            const u64 ci  = g[row ? 3 : 1];
            const u64 cin = g[row ? 6 : 4];
            const u64 nre = ffma2(cr, pre, fmul2(cin, pim));
            const u64 nim = ffma2(ci, pre, fmul2(cr,  pim));
            pre = nre; pim = nim;
        }
        #pragma unroll
        for (int v = 0; v < 16; ++v) {
            u64 vre = pre, vim = pim;
            #pragma unroll
            for (int bit = 0; bit < 4; ++bit) {
                const int row = (v >> bit) & 1;
                const u64* g = Ugp + (3 - bit) * 8;
                const u64 cr  = g[row ? 5 : 0];
                const u64 ci  = g[row ? 3 : 1];
                const u64 cin = g[row ? 6 : 4];
                const u64 nre = ffma2(cr, vre, fmul2(cin, vim));
                const u64 nim = ffma2(ci, vre, fmul2(cr,  vim));
                vre = nre; vim = nim;
            }
            st[haddr((v << 8) | t)] = make_ulonglong2(vre, vim);
        }
    }
    __syncthreads();

    u64 re[16], im[16];

    // ---- layers 1..2: 3 rounds each; round0->round1 exchange is warp-local ----
    for (int L = 1; L <= 2; ++L) {
        gather_apply<0>(st, Ugp, L, t, re, im);
        #pragma unroll
        for (int v = 0; v < 16; ++v) st[saddr(jidx<0>(t, v))] = make_ulonglong2(re[v], im[v]);
        __syncwarp();
        gather_apply<1>(st, Ugp, L, t, re, im);
        #pragma unroll
        for (int v = 0; v < 16; ++v) st[saddr(jidx<1>(t, v))] = make_ulonglong2(re[v], im[v]);
        __syncthreads();
        gather_apply<2>(st, Ugp, L, t, re, im);
        #pragma unroll
        for (int v = 0; v < 16; ++v) st[haddr(jidx<2>(t, v))] = make_ulonglong2(re[v], im[v]);
        __syncthreads();
    }

    // ---- layer 3: rounds 0,1; round 2 fused with measurement ----
    {
        gather_apply<0>(st, Ugp, 3, t, re, im);
        #pragma unroll
        for (int v = 0; v < 16; ++v) st[saddr(jidx<0>(t, v))] = make_ulonglong2(re[v], im[v]);
        __syncwarp();
        gather_apply<1>(st, Ugp, 3, t, re, im);
        #pragma unroll
        for (int v = 0; v < 16; ++v) st[saddr(jidx<1>(t, v))] = make_ulonglong2(re[v], im[v]);
        __syncthreads();
        gather_apply<2>(st, Ugp, 3, t, re, im);
    }

    // ---- measurement (packed) ----
    const u64 pone = pk2(1.f, 1.f), mone = pk2(-1.f, -1.f), zero = pk2(0.f, 0.f);
    u64 acc0 = zero, acc1 = zero, acc2 = zero, se = zero, so = zero;
    #pragma unroll
    for (int v = 0; v < 16; ++v) {
        const u64 p = ffma2(re[v], re[v], fmul2(im[v], im[v]));
        const int b3 = (v >> 3) & 1, b2 = (v >> 2) & 1, b1 = (v >> 1) & 1, bb = v & 1;
        acc0 = ffma2(p, b3 ? mone : pone, acc0);
        acc1 = ffma2(p, (b3 ^ b2) ? mone : pone, acc1);
        acc2 = ffma2(p, (b3 ^ b2 ^ b1) ? mone : pone, acc2);
        if (b3 ^ b2 ^ b1 ^ bb) so = ffma2(p, pone, so);
        else                   se = ffma2(p, pone, se);
    }
    const u64 dd = ffma2(so, mone, se);

    float a0[2], a1[2], a2[2], dv[2];
    up2(acc0, a0[0], a0[1]);
    up2(acc1, a1[0], a1[1]);
    up2(acc2, a2[0], a2[1]);
    up2(dd,   dv[0], dv[1]);

    const int t7 = (t >> 7) & 1, t6 = (t >> 6) & 1, t5 = (t >> 5) & 1, t4 = (t >> 4) & 1;
    const unsigned FULL = 0xffffffffu;
    #pragma unroll
    for (int e = 0; e < 2; ++e) {
        const float d = dv[e];
        float rr[8];
        rr[0] = a0[e]; rr[1] = a1[e]; rr[2] = a2[e]; rr[3] = d;
        rr[4] = t7 ? -d : d;
        rr[5] = (t7 ^ t6) ? -d : d;
        rr[6] = (t7 ^ t6 ^ t5) ? -d : d;
        rr[7] = (t7 ^ t6 ^ t5 ^ t4) ? -d : d;
        #pragma unroll
        for (int i = 0; i < 8; ++i) {
            float v = rr[i];
            #pragma unroll
            for (int o = 16; o > 0; o >>= 1) v += __shfl_xor_sync(FULL, v, o);
            if ((t & 31) == 0) red[e * 64 + (t >> 5) * 8 + i] = v;
        }
    }
    __syncthreads();
    if (t < 16) {
        const int e = t >> 3, i = t & 7;
        float s = 0.f;
        #pragma unroll
        for (int wp2 = 0; wp2 < 8; ++wp2) s += red[e * 64 + wp2 * 8 + i];
        out[(b0 + e) * 8 + i] = s * 3.14159265358979f;
    }
}

extern "C" void kernel_launch(void* const* d_in, const int* in_sizes, int n_in,
                              void* d_out, int out_size) {
    const float* x = (const float*)d_in[0];   // [B, 2]
    const float* w = (const float*)d_in[1];   // [4, 12, 3]
    float* out = (float*)d_out;               // [B, 8]
    const int B = in_sizes[0] / 2;
    cudaFuncSetAttribute(qnn_kernel, cudaFuncAttributeMaxDynamicSharedMemorySize, SMEM_TOTAL);
    qnn_kernel<<<B / 2, NT, SMEM_TOTAL>>>(x, w, out);
}